// round 6
// baseline (speedup 1.0000x reference)
#include <cuda_runtime.h>
#include <cstdint>

#define NB 32
#define NT 1024
#define ND 512
#define NU 64

// -------- scratch (device globals) --------
__device__ float g_C[2ull * NB * ND * 128];  // X^T@[w2|w3] fp32  (16.8MB)
__device__ float g_M[64ull * ND * NU];       // [sb][d][u] fp32   (8.4MB)
__device__ float g_E[2 * NB * NT];
__device__ float g_W[2 * NB * NT];

// -------- helpers --------
// split (x0,x1) -> packed f16x2 hi (lo half = x0) + packed residual lo
__device__ __forceinline__ void split_pair(float x0, float x1, uint32_t& hi, uint32_t& lo) {
    asm("cvt.rn.f16x2.f32 %0, %1, %2;" : "=r"(hi) : "f"(x1), "f"(x0));
    float h0, h1;
    asm("{ .reg .b16 a, b; mov.b32 {a, b}, %2; cvt.f32.f16 %0, a; cvt.f32.f16 %1, b; }"
        : "=f"(h0), "=f"(h1) : "r"(hi));
    float l0 = x0 - h0, l1 = x1 - h1;
    asm("cvt.rn.f16x2.f32 %0, %1, %2;" : "=r"(lo) : "f"(l1), "f"(l0));
}
__device__ __forceinline__ void mma_f16(float* c, const uint32_t* a, const uint32_t* b) {
    asm volatile(
        "mma.sync.aligned.m16n8k16.row.col.f32.f16.f16.f32 "
        "{%0,%1,%2,%3}, {%4,%5,%6,%7}, {%8,%9}, {%0,%1,%2,%3};"
        : "+f"(c[0]), "+f"(c[1]), "+f"(c[2]), "+f"(c[3])
        : "r"(a[0]), "r"(a[1]), "r"(a[2]), "r"(a[3]), "r"(b[0]), "r"(b[1]));
}
// smem rows: 16 k-halfs = 8 words + 1 pad word -> 9 words (36B) per row
#define ROWW 9

// ============================================================================
// K1: C[s][b] = X_s[b]^T @ [w2|w3]   M=128(d) N=128(u) K=1024(t)
// 8 warps (2M x 4N), warp tile 64x32, Kc=16.
// Pre-split fp16 smem (hi/lo), k-pair packed: 1 LDS.32 per fragment reg.
// ============================================================================
__global__ void __launch_bounds__(256, 2) k1_xtw(const float* __restrict__ x1,
                                                 const float* __restrict__ x2,
                                                 const float* __restrict__ w2,
                                                 const float* __restrict__ w3) {
    __shared__ __align__(16) uint32_t sAh[2][128][ROWW];  // [d][t-pair words]
    __shared__ __align__(16) uint32_t sAl[2][128][ROWW];
    __shared__ __align__(16) uint32_t sBh[2][128][ROWW];  // [u][t-pair words]
    __shared__ __align__(16) uint32_t sBl[2][128][ROWW];
    const int tid = threadIdx.x, wid = tid >> 5, lane = tid & 31;
    const int gid = lane >> 2, tig = lane & 3;
    const int dt = blockIdx.x, b = blockIdx.y, s = blockIdx.z;
    const float* __restrict__ X = s ? x2 : x1;
    const int d0 = dt * 128;
    const int wm = (wid >> 2) * 64, wn = (wid & 3) * 32;
    const int tp = tid >> 5, dc = (tid & 31) * 4;  // loader coords

    float acc[4][4][4];
#pragma unroll
    for (int i = 0; i < 4; i++)
#pragma unroll
        for (int j = 0; j < 4; j++)
#pragma unroll
            for (int q = 0; q < 4; q++) acc[i][j][q] = 0.f;

    float4 ra[2][2], rb[2][2];
    const float* srcB0 = (dc < 64) ? (w2 + dc) : (w3 + (dc - 64));

    auto ldg = [&](int ch, int rs) {
        const int k0 = ch * 16;
        ra[rs][0] = *(const float4*)(X + ((size_t)b * NT + k0 + 2 * tp) * ND + d0 + dc);
        ra[rs][1] = *(const float4*)(X + ((size_t)b * NT + k0 + 2 * tp + 1) * ND + d0 + dc);
        rb[rs][0] = *(const float4*)(srcB0 + (size_t)(k0 + 2 * tp) * NU);
        rb[rs][1] = *(const float4*)(srcB0 + (size_t)(k0 + 2 * tp + 1) * NU);
    };
    auto sts = [&](int bi, int rs) {
        const float* a0 = &ra[rs][0].x;
        const float* a1 = &ra[rs][1].x;
        const float* b0 = &rb[rs][0].x;
        const float* b1 = &rb[rs][1].x;
#pragma unroll
        for (int j = 0; j < 4; j++) {
            uint32_t hi, lo;
            split_pair(a0[j], a1[j], hi, lo);
            sAh[bi][dc + j][tp] = hi;
            sAl[bi][dc + j][tp] = lo;
            split_pair(b0[j], b1[j], hi, lo);
            sBh[bi][dc + j][tp] = hi;
            sBl[bi][dc + j][tp] = lo;
        }
    };

    ldg(0, 0);
    for (int ch = 0; ch < 64; ch++) {
        const int bi = ch & 1, rs = ch & 1;
        if (ch + 1 < 64) ldg(ch + 1, rs ^ 1);
        sts(bi, rs);
        __syncthreads();
        uint32_t bh[4][2], bl[4][2];
#pragma unroll
        for (int ni = 0; ni < 4; ni++) {
            const int un = wn + ni * 8 + gid;
            bh[ni][0] = sBh[bi][un][tig];
            bh[ni][1] = sBh[bi][un][tig + 4];
            bl[ni][0] = sBl[bi][un][tig];
            bl[ni][1] = sBl[bi][un][tig + 4];
        }
#pragma unroll
        for (int mi = 0; mi < 4; mi++) {
            const int dm = wm + mi * 16 + gid;
            uint32_t ah[4], al[4];
            ah[0] = sAh[bi][dm][tig];
            ah[1] = sAh[bi][dm + 8][tig];
            ah[2] = sAh[bi][dm][tig + 4];
            ah[3] = sAh[bi][dm + 8][tig + 4];
            al[0] = sAl[bi][dm][tig];
            al[1] = sAl[bi][dm + 8][tig];
            al[2] = sAl[bi][dm][tig + 4];
            al[3] = sAl[bi][dm + 8][tig + 4];
#pragma unroll
            for (int ni = 0; ni < 4; ni++) {
                mma_f16(acc[mi][ni], ah, bh[ni]);
                mma_f16(acc[mi][ni], al, bh[ni]);
                mma_f16(acc[mi][ni], ah, bl[ni]);
            }
        }
        __syncthreads();
    }
    float* dst = g_C + (size_t)(s * NB + b) * ND * 128 + (size_t)d0 * 128;
#pragma unroll
    for (int mi = 0; mi < 4; mi++) {
        int r0 = wm + mi * 16 + gid, r1 = r0 + 8;
#pragma unroll
        for (int ni = 0; ni < 4; ni++) {
            int col = wn + ni * 8 + 2 * tig;
            *(float2*)(dst + (size_t)r0 * 128 + col) =
                make_float2(acc[mi][ni][0], acc[mi][ni][1]);
            *(float2*)(dst + (size_t)r1 * 128 + col) =
                make_float2(acc[mi][ni][2], acc[mi][ni][3]);
        }
    }
}

// ============================================================================
// K_prep: M[sb][d][u] = C[1-s][b][d][u] + C[s][b][d][64+u] + w1[d][u]
// ============================================================================
__global__ void __launch_bounds__(256) k_prep(const float* __restrict__ w1) {
    size_t i = (size_t)blockIdx.x * 256 + threadIdx.x;  // 2,097,152 total
    int u = (int)(i & 63);
    int d = (int)((i >> 6) & (ND - 1));
    int sb = (int)(i >> 15);
    int s = sb >> 5, b = sb & 31;
    float v = g_C[(((size_t)((1 - s) * NB + b) * ND + d) << 7) + u] +
              g_C[(((size_t)sb * ND + d) << 7) + 64 + u] + w1[d * NU + u];
    g_M[i] = v;
}

// ============================================================================
// K2: e = 10*sum_u tanh(X@M)*we    M=128(t) N=64(u) K=512(d)
// 8 warps (4M x 2N), warp tile 32x32, Kc=16, pre-split fp16 smem.
// ============================================================================
__global__ void __launch_bounds__(256, 2) k2_he(const float* __restrict__ x1,
                                                const float* __restrict__ x2,
                                                const float* __restrict__ we) {
    __shared__ __align__(16) uint32_t sAh[2][128][ROWW];  // [t][d-pair words]
    __shared__ __align__(16) uint32_t sAl[2][128][ROWW];
    __shared__ __align__(16) uint32_t sBh[2][64][ROWW];   // [u][d-pair words]
    __shared__ __align__(16) uint32_t sBl[2][64][ROWW];
    __shared__ float wes[64];
    __shared__ float red[128][2];
    const int tid = threadIdx.x, wid = tid >> 5, lane = tid & 31;
    const int gid = lane >> 2, tig = lane & 3;
    const int tt = blockIdx.x, b = blockIdx.y, s = blockIdx.z;
    const float* __restrict__ X = s ? x2 : x1;
    const int t0 = tt * 128, sb = s * NB + b;
    const int wm = (wid >> 1) * 32, wn = (wid & 1) * 32;
    // A loader: row t = tid>>1, col half = tid&1 (8 d's)
    const int at = tid >> 1, ahalf = tid & 1;
    // B loader: d-pair = wid, u0 = lane*2
    const int bdp = wid, bu0 = lane * 2;

    if (tid < 64) wes[tid] = we[tid];

    float acc[2][4][4];
#pragma unroll
    for (int i = 0; i < 2; i++)
#pragma unroll
        for (int j = 0; j < 4; j++)
#pragma unroll
            for (int q = 0; q < 4; q++) acc[i][j][q] = 0.f;

    const float* __restrict__ Mb = g_M + (size_t)sb * ND * NU;

    float4 ra[2][2];
    float2 rb[2][2];
    auto ldg = [&](int ch, int rs) {
        const int k0 = ch * 16;
        ra[rs][0] = *(const float4*)(X + ((size_t)b * NT + t0 + at) * ND + k0 + ahalf * 8);
        ra[rs][1] = *(const float4*)(X + ((size_t)b * NT + t0 + at) * ND + k0 + ahalf * 8 + 4);
        rb[rs][0] = *(const float2*)(Mb + (size_t)(k0 + 2 * bdp) * NU + bu0);
        rb[rs][1] = *(const float2*)(Mb + (size_t)(k0 + 2 * bdp + 1) * NU + bu0);
    };
    auto sts = [&](int bi, int rs) {
        const float* a0 = &ra[rs][0].x;
        const float* a1 = &ra[rs][1].x;
        uint32_t hi, lo;
#pragma unroll
        for (int j = 0; j < 2; j++) {  // pairs (d0,d1),(d2,d3) of first float4
            split_pair(a0[2 * j], a0[2 * j + 1], hi, lo);
            sAh[bi][at][ahalf * 4 + j] = hi;
            sAl[bi][at][ahalf * 4 + j] = lo;
            split_pair(a1[2 * j], a1[2 * j + 1], hi, lo);
            sAh[bi][at][ahalf * 4 + 2 + j] = hi;
            sAl[bi][at][ahalf * 4 + 2 + j] = lo;
        }
        split_pair(rb[rs][0].x, rb[rs][1].x, hi, lo);
        sBh[bi][bu0][bdp] = hi;
        sBl[bi][bu0][bdp] = lo;
        split_pair(rb[rs][0].y, rb[rs][1].y, hi, lo);
        sBh[bi][bu0 + 1][bdp] = hi;
        sBl[bi][bu0 + 1][bdp] = lo;
    };

    ldg(0, 0);
    for (int ch = 0; ch < 32; ch++) {
        const int bi = ch & 1, rs = ch & 1;
        if (ch + 1 < 32) ldg(ch + 1, rs ^ 1);
        sts(bi, rs);
        __syncthreads();
        uint32_t bh[4][2], bl[4][2];
#pragma unroll
        for (int ni = 0; ni < 4; ni++) {
            const int un = wn + ni * 8 + gid;
            bh[ni][0] = sBh[bi][un][tig];
            bh[ni][1] = sBh[bi][un][tig + 4];
            bl[ni][0] = sBl[bi][un][tig];
            bl[ni][1] = sBl[bi][un][tig + 4];
        }
#pragma unroll
        for (int mi = 0; mi < 2; mi++) {
            const int tr = wm + mi * 16 + gid;
            uint32_t ah[4], al[4];
            ah[0] = sAh[bi][tr][tig];
            ah[1] = sAh[bi][tr + 8][tig];
            ah[2] = sAh[bi][tr][tig + 4];
            ah[3] = sAh[bi][tr + 8][tig + 4];
            al[0] = sAl[bi][tr][tig];
            al[1] = sAl[bi][tr + 8][tig];
            al[2] = sAl[bi][tr][tig + 4];
            al[3] = sAl[bi][tr + 8][tig + 4];
#pragma unroll
            for (int ni = 0; ni < 4; ni++) {
                mma_f16(acc[mi][ni], ah, bh[ni]);
                mma_f16(acc[mi][ni], al, bh[ni]);
                mma_f16(acc[mi][ni], ah, bl[ni]);
            }
        }
        __syncthreads();
    }
    // epilogue: e(t) = 10 * sum_u tanh(h[t,u]) * we[u]
#pragma unroll
    for (int mi = 0; mi < 2; mi++) {
        int r0 = wm + mi * 16 + gid, r1 = r0 + 8;
        float p0 = 0.f, p1 = 0.f;
#pragma unroll
        for (int ni = 0; ni < 4; ni++) {
            int u = wn + ni * 8 + 2 * tig;
            p0 += tanhf(acc[mi][ni][0]) * wes[u] + tanhf(acc[mi][ni][1]) * wes[u + 1];
            p1 += tanhf(acc[mi][ni][2]) * wes[u] + tanhf(acc[mi][ni][3]) * wes[u + 1];
        }
        p0 += __shfl_xor_sync(0xffffffffu, p0, 1);
        p0 += __shfl_xor_sync(0xffffffffu, p0, 2);
        p1 += __shfl_xor_sync(0xffffffffu, p1, 1);
        p1 += __shfl_xor_sync(0xffffffffu, p1, 2);
        if (tig == 0) {
            red[r0][wid & 1] = p0;
            red[r1][wid & 1] = p1;
        }
    }
    __syncthreads();
    if (tid < 128) {
        g_E[sb * NT + t0 + tid] = 10.0f * (red[tid][0] + red[tid][1]);
    }
}

// ============================================================================
// K3: softmax over T per (s,b) (unstabilized, matches reference)
// ============================================================================
__global__ void __launch_bounds__(256) k3_softmax() {
    const int sb = blockIdx.x, tid = threadIdx.x;
    __shared__ float ssum[8];
    float a[4], lsum = 0.f;
#pragma unroll
    for (int i = 0; i < 4; i++) {
        a[i] = expf(g_E[sb * NT + tid + i * 256]);
        lsum += a[i];
    }
#pragma unroll
    for (int o = 16; o; o >>= 1) lsum += __shfl_xor_sync(0xffffffffu, lsum, o);
    if ((tid & 31) == 0) ssum[tid >> 5] = lsum;
    __syncthreads();
    if (tid == 0) {
        float sT = 0.f;
#pragma unroll
        for (int q = 0; q < 8; q++) sT += ssum[q];
        ssum[0] = 1.0f / (sT + 1e-7f);
    }
    __syncthreads();
    float inv = ssum[0];
#pragma unroll
    for (int i = 0; i < 4; i++) g_W[sb * NT + tid + i * 256] = a[i] * inv;
}

// ============================================================================
// K4: out = X * ww  (float4 streaming)
// ============================================================================
__global__ void __launch_bounds__(256) k4_scale(const float* __restrict__ x1,
                                                const float* __restrict__ x2,
                                                float* __restrict__ out) {
    size_t f = (size_t)blockIdx.x * 256 + threadIdx.x;
    int d4 = (int)(f & 127);
    int t = (int)((f >> 7) & 1023);
    int sb = (int)(f >> 17);
    const float* __restrict__ X = (sb >= NB) ? x2 : x1;
    int b = sb & 31;
    float w = g_W[sb * NT + t];
    float4 v = *(const float4*)(X + ((size_t)b * NT + t) * ND + (d4 << 2));
    v.x *= w; v.y *= w; v.z *= w; v.w *= w;
    ((float4*)out)[f] = v;
}

extern "C" void kernel_launch(void* const* d_in, const int* in_sizes, int n_in,
                              void* d_out, int out_size) {
    const float* x1 = (const float*)d_in[0];
    const float* x2 = (const float*)d_in[1];
    const float* w1 = (const float*)d_in[2];
    const float* w2 = (const float*)d_in[3];
    const float* w3 = (const float*)d_in[4];
    const float* we = (const float*)d_in[5];
    float* out = (float*)d_out;

    dim3 g1(ND / 128, NB, 2);
    k1_xtw<<<g1, 256>>>(x1, x2, w2, w3);

    k_prep<<<(2 * NB * ND * NU) / 256, 256>>>(w1);

    dim3 g2(NT / 128, NB, 2);
    k2_he<<<g2, 256>>>(x1, x2, we);

    k3_softmax<<<2 * NB, 256>>>();

    k4_scale<<<(2u * NB * NT * (ND / 4)) / 256, 256>>>(x1, x2, out);
}

// round 8
// speedup vs baseline: 1.6470x; 1.6470x over previous
#include <cuda_runtime.h>
#include <cstdint>

#define NB 32
#define NT 1024
#define ND 512
#define NU 64

// -------- scratch (device globals) --------
__device__ float g_C[2ull * NB * ND * 128];   // X^T@[w2|w3] fp32  (16.8MB)
__device__ uint32_t g_WH[512 * 128];          // [t-pair][u] packed f16x2 hi of [w2|w3]
__device__ uint32_t g_WL[512 * 128];          //                  residual lo
__device__ uint32_t g_MH[64ull * 256 * 64];   // [sb][d-pair][u] packed f16x2 hi of M
__device__ uint32_t g_ML[64ull * 256 * 64];
__device__ float g_E[2 * NB * NT];
__device__ float g_W[2 * NB * NT];

// -------- helpers --------
__device__ __forceinline__ uint32_t smem_u32(const void* p) {
    uint32_t a;
    asm("{ .reg .u64 t; cvta.to.shared.u64 t, %1; cvt.u32.u64 %0, t; }" : "=r"(a) : "l"(p));
    return a;
}
// split (x0,x1) -> packed f16x2 hi (lo half = x0) + packed residual lo
__device__ __forceinline__ void split_pair(float x0, float x1, uint32_t& hi, uint32_t& lo) {
    asm("cvt.rn.f16x2.f32 %0, %1, %2;" : "=r"(hi) : "f"(x1), "f"(x0));
    float h0, h1;
    asm("{ .reg .b16 a, b; mov.b32 {a, b}, %2; cvt.f32.f16 %0, a; cvt.f32.f16 %1, b; }"
        : "=f"(h0), "=f"(h1) : "r"(hi));
    float l0 = x0 - h0, l1 = x1 - h1;
    asm("cvt.rn.f16x2.f32 %0, %1, %2;" : "=r"(lo) : "f"(l1), "f"(l0));
}
__device__ __forceinline__ void mma_f16(float* c, const uint32_t* a, const uint32_t* b) {
    asm volatile(
        "mma.sync.aligned.m16n8k16.row.col.f32.f16.f16.f32 "
        "{%0,%1,%2,%3}, {%4,%5,%6,%7}, {%8,%9}, {%0,%1,%2,%3};"
        : "+f"(c[0]), "+f"(c[1]), "+f"(c[2]), "+f"(c[3])
        : "r"(a[0]), "r"(a[1]), "r"(a[2]), "r"(a[3]), "r"(b[0]), "r"(b[1]));
}
__device__ __forceinline__ void cp16(uint32_t dst, const void* src) {
    asm volatile("cp.async.cg.shared.global [%0], [%1], 16;" :: "r"(dst), "l"(src));
}
#define CP_COMMIT() asm volatile("cp.async.commit_group;" ::: "memory")
#define CP_WAIT1() asm volatile("cp.async.wait_group 1;" ::: "memory")
#define CP_WAIT0() asm volatile("cp.async.wait_group 0;" ::: "memory")

// ============================================================================
// K0: pre-split [w2|w3] into packed f16x2 t-pair words.
// ============================================================================
__global__ void __launch_bounds__(256) k0_wsplit(const float* __restrict__ w2,
                                                 const float* __restrict__ w3) {
    int i = blockIdx.x * 256 + threadIdx.x;  // 512*128
    int u = i & 127, tp = i >> 7;
    const float* W = (u < 64) ? (w2 + u) : (w3 + (u - 64));
    float v0 = W[(size_t)(2 * tp) * NU];
    float v1 = W[(size_t)(2 * tp + 1) * NU];
    uint32_t hi, lo;
    split_pair(v0, v1, hi, lo);
    g_WH[i] = hi;
    g_WL[i] = lo;
}

// ============================================================================
// K1: C[s][b] = X_s[b]^T @ [w2|w3]   M=128(d) N=128(u) K=1024(t)
// 8 warps (2M x 4N), warp tile 64x32, Kc=16 double-buffered cp.async.
// A: fp32 smem (stride 132), split at fragment load (as R5).
// B: pre-split packed fp16 words, direct LDS fragments (stride 136).
// ============================================================================
#define K1S 132
#define K1BS 136
__global__ void __launch_bounds__(256, 2) k1_xtw(const float* __restrict__ x1,
                                                 const float* __restrict__ x2) {
    __shared__ __align__(16) float sA[2][16][K1S];        // [t][d]
    __shared__ __align__(16) uint32_t sB[2][2][8][K1BS];  // [buf][hi/lo][t-pair][u]
    const int tid = threadIdx.x, wid = tid >> 5, lane = tid & 31;
    const int gid = lane >> 2, tig = lane & 3;
    const int dt = blockIdx.x, b = blockIdx.y, s = blockIdx.z;
    const float* __restrict__ X = s ? x2 : x1;
    const int d0 = dt * 128;
    const int wm = (wid >> 2) * 64, wn = (wid & 3) * 32;

    float acc[4][4][4];
#pragma unroll
    for (int i = 0; i < 4; i++)
#pragma unroll
        for (int j = 0; j < 4; j++)
#pragma unroll
            for (int q = 0; q < 4; q++) acc[i][j][q] = 0.f;

    const uint32_t aB = smem_u32(&sA[0][0][0]);
    const uint32_t bB = smem_u32(&sB[0][0][0][0]);
    const uint32_t aBuf = 16 * K1S * 4;
    const uint32_t bBuf = 2 * 8 * K1BS * 4;

    auto issue = [&](int ch, int bi) {
        const int k0 = ch * 16;
#pragma unroll
        for (int it = 0; it < 2; it++) {
            int ff = tid + it * 256;
            int r = ff >> 5, c = (ff & 31) * 4;
            cp16(aB + bi * aBuf + (uint32_t)(r * K1S + c) * 4,
                 X + ((size_t)b * NT + k0 + r) * ND + d0 + c);
        }
#pragma unroll
        for (int it = 0; it < 2; it++) {
            int ff = tid + it * 256;
            int sp = ff >> 8, r = (ff >> 5) & 7, c = (ff & 31) * 4;
            const uint32_t* src = (sp ? g_WL : g_WH) + (size_t)(ch * 8 + r) * 128 + c;
            cp16(bB + bi * bBuf + (uint32_t)((sp * 8 + r) * K1BS + c) * 4, src);
        }
        CP_COMMIT();
    };

    issue(0, 0);
    for (int ch = 0; ch < 64; ch++) {
        if (ch + 1 < 64) {
            issue(ch + 1, (ch + 1) & 1);
            CP_WAIT1();
        } else {
            CP_WAIT0();
        }
        __syncthreads();
        const int bi = ch & 1;
        const float(*A)[K1S] = sA[bi];
        uint32_t bh[4][2], bl[4][2];
#pragma unroll
        for (int ni = 0; ni < 4; ni++) {
            const int un = wn + ni * 8 + gid;
            bh[ni][0] = sB[bi][0][tig][un];
            bh[ni][1] = sB[bi][0][tig + 4][un];
            bl[ni][0] = sB[bi][1][tig][un];
            bl[ni][1] = sB[bi][1][tig + 4][un];
        }
#pragma unroll
        for (int mi = 0; mi < 4; mi++) {
            const int dm = wm + mi * 16 + gid;
            uint32_t ah[4], al[4];
            split_pair(A[2 * tig][dm], A[2 * tig + 1][dm], ah[0], al[0]);
            split_pair(A[2 * tig][dm + 8], A[2 * tig + 1][dm + 8], ah[1], al[1]);
            split_pair(A[2 * tig + 8][dm], A[2 * tig + 9][dm], ah[2], al[2]);
            split_pair(A[2 * tig + 8][dm + 8], A[2 * tig + 9][dm + 8], ah[3], al[3]);
#pragma unroll
            for (int ni = 0; ni < 4; ni++) {
                mma_f16(acc[mi][ni], ah, bh[ni]);
                mma_f16(acc[mi][ni], al, bh[ni]);
                mma_f16(acc[mi][ni], ah, bl[ni]);
            }
        }
        __syncthreads();
    }
    float* dst = g_C + (size_t)(s * NB + b) * ND * 128 + (size_t)d0 * 128;
#pragma unroll
    for (int mi = 0; mi < 4; mi++) {
        int r0 = wm + mi * 16 + gid, r1 = r0 + 8;
#pragma unroll
        for (int ni = 0; ni < 4; ni++) {
            int col = wn + ni * 8 + 2 * tig;
            *(float2*)(dst + (size_t)r0 * 128 + col) =
                make_float2(acc[mi][ni][0], acc[mi][ni][1]);
            *(float2*)(dst + (size_t)r1 * 128 + col) =
                make_float2(acc[mi][ni][2], acc[mi][ni][3]);
        }
    }
}

// ============================================================================
// K_prep: M[sb][d][u] = C[1-s][b][d][u] + C[s][b][d][64+u] + w1[d][u]
// -> packed f16x2 d-pair words g_MH/g_ML [sb][dp][u]
// ============================================================================
__global__ void __launch_bounds__(256) k_prep(const float* __restrict__ w1) {
    int i = blockIdx.x * 256 + threadIdx.x;  // 64*256*64 = 1,048,576
    int u = i & 63;
    int dp = (i >> 6) & 255;
    int sb = i >> 14;
    int s = sb >> 5, b = sb & 31;
    const float* C0 = g_C + ((size_t)((1 - s) * NB + b) * ND << 7);
    const float* C1 = g_C + ((size_t)sb * ND << 7);
    int d0 = 2 * dp, d1 = 2 * dp + 1;
    float m0 = C0[((size_t)d0 << 7) + u] + C1[((size_t)d0 << 7) + 64 + u] + w1[d0 * NU + u];
    float m1 = C0[((size_t)d1 << 7) + u] + C1[((size_t)d1 << 7) + 64 + u] + w1[d1 * NU + u];
    uint32_t hi, lo;
    split_pair(m0, m1, hi, lo);
    g_MH[i] = hi;
    g_ML[i] = lo;
}

// ============================================================================
// K2: e = 10*sum_u tanh(X@M)*we    M=128(t) N=64(u) K=512(d)
// 8 warps (4M x 2N), warp tile 32x32, Kc=16 double-buffered.
// A: fp32 smem (as R5). B: pre-split packed fp16 words (stride 72).
// ============================================================================
#define K2AS 20
#define K2BS 72
__global__ void __launch_bounds__(256, 2) k2_he(const float* __restrict__ x1,
                                                const float* __restrict__ x2,
                                                const float* __restrict__ we) {
    __shared__ __align__(16) float sA[2][128][K2AS];      // [t][d]
    __shared__ __align__(16) uint32_t sB[2][2][8][K2BS];  // [buf][hi/lo][d-pair][u]
    __shared__ float wes[64];
    __shared__ float red[128][2];
    const int tid = threadIdx.x, wid = tid >> 5, lane = tid & 31;
    const int gid = lane >> 2, tig = lane & 3;
    const int tt = blockIdx.x, b = blockIdx.y, s = blockIdx.z;
    const float* __restrict__ X = s ? x2 : x1;
    const int t0 = tt * 128, sb = s * NB + b;
    const int wm = (wid >> 1) * 32, wn = (wid & 1) * 32;

    if (tid < 64) wes[tid] = we[tid];

    float acc[2][4][4];
#pragma unroll
    for (int i = 0; i < 2; i++)
#pragma unroll
        for (int j = 0; j < 4; j++)
#pragma unroll
            for (int q = 0; q < 4; q++) acc[i][j][q] = 0.f;

    const uint32_t aB = smem_u32(&sA[0][0][0]);
    const uint32_t bB = smem_u32(&sB[0][0][0][0]);
    const uint32_t bBuf = 2 * 8 * K2BS * 4;
    const size_t mBase = (size_t)sb * 256 * 64;

    auto issue = [&](int ch, int bi) {
        const int k0 = ch * 16;
#pragma unroll
        for (int it = 0; it < 2; it++) {
            int ff = tid + it * 256;
            int r = ff >> 2, c = (ff & 3) * 4;
            cp16(aB + (uint32_t)(bi * 128 * K2AS + r * K2AS + c) * 4,
                 X + ((size_t)b * NT + t0 + r) * ND + k0 + c);
        }
        {
            int sp = tid >> 7, r = (tid >> 4) & 7, c = (tid & 15) * 4;
            const uint32_t* src = (sp ? g_ML : g_MH) + mBase + (size_t)(ch * 8 + r) * 64 + c;
            cp16(bB + bi * bBuf + (uint32_t)((sp * 8 + r) * K2BS + c) * 4, src);
        }
        CP_COMMIT();
    };

    issue(0, 0);
    for (int ch = 0; ch < 32; ch++) {
        if (ch + 1 < 32) {
            issue(ch + 1, (ch + 1) & 1);
            CP_WAIT1();
        } else {
            CP_WAIT0();
        }
        __syncthreads();
        const int bi = ch & 1;
        const float(*A)[K2AS] = sA[bi];
        uint32_t bh[4][2], bl[4][2];
#pragma unroll
        for (int ni = 0; ni < 4; ni++) {
            const int un = wn + ni * 8 + gid;
            bh[ni][0] = sB[bi][0][tig][un];
            bh[ni][1] = sB[bi][0][tig + 4][un];
            bl[ni][0] = sB[bi][1][tig][un];
            bl[ni][1] = sB[bi][1][tig + 4][un];
        }
#pragma unroll
        for (int mi = 0; mi < 2; mi++) {
            const int tr = wm + mi * 16 + gid;
            uint32_t ah[4], al[4];
            {
                float2 v = *(const float2*)&A[tr][2 * tig];
                split_pair(v.x, v.y, ah[0], al[0]);
            }
            {
                float2 v = *(const float2*)&A[tr + 8][2 * tig];
                split_pair(v.x, v.y, ah[1], al[1]);
            }
            {
                float2 v = *(const float2*)&A[tr][2 * tig + 8];
                split_pair(v.x, v.y, ah[2], al[2]);
            }
            {
                float2 v = *(const float2*)&A[tr + 8][2 * tig + 8];
                split_pair(v.x, v.y, ah[3], al[3]);
            }
#pragma unroll
            for (int ni = 0; ni < 4; ni++) {
                mma_f16(acc[mi][ni], ah, bh[ni]);
                mma_f16(acc[mi][ni], al, bh[ni]);
                mma_f16(acc[mi][ni], ah, bl[ni]);
            }
        }
        __syncthreads();
    }
    // epilogue: e(t) = 10 * sum_u tanh(h[t,u]) * we[u]
#pragma unroll
    for (int mi = 0; mi < 2; mi++) {
        int r0 = wm + mi * 16 + gid, r1 = r0 + 8;
        float p0 = 0.f, p1 = 0.f;
#pragma unroll
        for (int ni = 0; ni < 4; ni++) {
            int u = wn + ni * 8 + 2 * tig;
            p0 += tanhf(acc[mi][ni][0]) * wes[u] + tanhf(acc[mi][ni][1]) * wes[u + 1];
            p1 += tanhf(acc[mi][ni][2]) * wes[u] + tanhf(acc[mi][ni][3]) * wes[u + 1];
        }
        p0 += __shfl_xor_sync(0xffffffffu, p0, 1);
        p0 += __shfl_xor_sync(0xffffffffu, p0, 2);
        p1 += __shfl_xor_sync(0xffffffffu, p1, 1);
        p1 += __shfl_xor_sync(0xffffffffu, p1, 2);
        if (tig == 0) {
            red[r0][wid & 1] = p0;
            red[r1][wid & 1] = p1;
        }
    }
    __syncthreads();
    if (tid < 128) {
        g_E[sb * NT + t0 + tid] = 10.0f * (red[tid][0] + red[tid][1]);
    }
}

// ============================================================================
// K3: softmax over T per (s,b) (unstabilized, matches reference)
// ============================================================================
__global__ void __launch_bounds__(256) k3_softmax() {
    const int sb = blockIdx.x, tid = threadIdx.x;
    __shared__ float ssum[8];
    float a[4], lsum = 0.f;
#pragma unroll
    for (int i = 0; i < 4; i++) {
        a[i] = expf(g_E[sb * NT + tid + i * 256]);
        lsum += a[i];
    }
#pragma unroll
    for (int o = 16; o; o >>= 1) lsum += __shfl_xor_sync(0xffffffffu, lsum, o);
    if ((tid & 31) == 0) ssum[tid >> 5] = lsum;
    __syncthreads();
    if (tid == 0) {
        float sT = 0.f;
#pragma unroll
        for (int q = 0; q < 8; q++) sT += ssum[q];
        ssum[0] = 1.0f / (sT + 1e-7f);
    }
    __syncthreads();
    float inv = ssum[0];
#pragma unroll
    for (int i = 0; i < 4; i++) g_W[sb * NT + tid + i * 256] = a[i] * inv;
}

// ============================================================================
// K4: out = X * ww  (float4 streaming)
// ============================================================================
__global__ void __launch_bounds__(256) k4_scale(const float* __restrict__ x1,
                                                const float* __restrict__ x2,
                                                float* __restrict__ out) {
    size_t f = (size_t)blockIdx.x * 256 + threadIdx.x;
    int d4 = (int)(f & 127);
    int t = (int)((f >> 7) & 1023);
    int sb = (int)(f >> 17);
    const float* __restrict__ X = (sb >= NB) ? x2 : x1;
    int b = sb & 31;
    float w = g_W[sb * NT + t];
    float4 v = *(const float4*)(X + ((size_t)b * NT + t) * ND + (d4 << 2));
    v.x *= w; v.y *= w; v.z *= w; v.w *= w;
    ((float4*)out)[f] = v;
}

extern "C" void kernel_launch(void* const* d_in, const int* in_sizes, int n_in,
                              void* d_out, int out_size) {
    const float* x1 = (const float*)d_in[0];
    const float* x2 = (const float*)d_in[1];
    const float* w1 = (const float*)d_in[2];
    const float* w2 = (const float*)d_in[3];
    const float* w3 = (const float*)d_in[4];
    const float* we = (const float*)d_in[5];
    float* out = (float*)d_out;

    k0_wsplit<<<(512 * 128) / 256, 256>>>(w2, w3);

    dim3 g1(ND / 128, NB, 2);
    k1_xtw<<<g1, 256>>>(x1, x2);

    k_prep<<<(64 * 256 * 64) / 256, 256>>>(w1);

    dim3 g2(NT / 128, NB, 2);
    k2_he<<<g2, 256>>>(x1, x2, we);

    k3_softmax<<<2 * NB, 256>>>();

    k4_scale<<<(2u * NB * NT * (ND / 4)) / 256, 256>>>(x1, x2, out);
}

// round 12
// speedup vs baseline: 1.6959x; 1.0297x over previous
#include <cuda_runtime.h>
#include <cstdint>

#define NB 32
#define NT 1024
#define ND 512
#define NU 64

// -------- scratch (device globals) --------
__device__ float g_C[2ull * NB * ND * 128];   // X^T@[w2|w3] fp32  (16.8MB)
__device__ uint32_t g_WH[512 * 128];          // [t-pair][u] packed f16x2 hi of [w2|w3]
__device__ uint32_t g_WL[512 * 128];          //                  residual lo
__device__ uint32_t g_MH[64ull * 256 * 64];   // [sb][d-pair][u] packed f16x2 hi of M
__device__ uint32_t g_ML[64ull * 256 * 64];
__device__ float g_E[2 * NB * NT];
__device__ float g_W[2 * NB * NT];

// -------- helpers --------
__device__ __forceinline__ uint32_t smem_u32(const void* p) {
    uint32_t a;
    asm("{ .reg .u64 t; cvta.to.shared.u64 t, %1; cvt.u32.u64 %0, t; }" : "=r"(a) : "l"(p));
    return a;
}
// split (x0,x1) -> packed f16x2 hi (lo half = x0) + packed residual lo
__device__ __forceinline__ void split_pair(float x0, float x1, uint32_t& hi, uint32_t& lo) {
    asm("cvt.rn.f16x2.f32 %0, %1, %2;" : "=r"(hi) : "f"(x1), "f"(x0));
    float h0, h1;
    asm("{ .reg .b16 a, b; mov.b32 {a, b}, %2; cvt.f32.f16 %0, a; cvt.f32.f16 %1, b; }"
        : "=f"(h0), "=f"(h1) : "r"(hi));
    float l0 = x0 - h0, l1 = x1 - h1;
    asm("cvt.rn.f16x2.f32 %0, %1, %2;" : "=r"(lo) : "f"(l1), "f"(l0));
}
__device__ __forceinline__ void mma_f16(float* c, const uint32_t* a, const uint32_t* b) {
    asm volatile(
        "mma.sync.aligned.m16n8k16.row.col.f32.f16.f16.f32 "
        "{%0,%1,%2,%3}, {%4,%5,%6,%7}, {%8,%9}, {%0,%1,%2,%3};"
        : "+f"(c[0]), "+f"(c[1]), "+f"(c[2]), "+f"(c[3])
        : "r"(a[0]), "r"(a[1]), "r"(a[2]), "r"(a[3]), "r"(b[0]), "r"(b[1]));
}
__device__ __forceinline__ void cp16(uint32_t dst, const void* src) {
    asm volatile("cp.async.cg.shared.global [%0], [%1], 16;" :: "r"(dst), "l"(src));
}
#define CP_COMMIT() asm volatile("cp.async.commit_group;" ::: "memory")
#define CP_WAIT1() asm volatile("cp.async.wait_group 1;" ::: "memory")
#define CP_WAIT0() asm volatile("cp.async.wait_group 0;" ::: "memory")

// ============================================================================
// K0: pre-split [w2|w3] into packed f16x2 t-pair words.
// ============================================================================
__global__ void __launch_bounds__(256) k0_wsplit(const float* __restrict__ w2,
                                                 const float* __restrict__ w3) {
    int i = blockIdx.x * 256 + threadIdx.x;  // 512*128
    int u = i & 127, tp = i >> 7;
    const float* W = (u < 64) ? (w2 + u) : (w3 + (u - 64));
    float v0 = W[(size_t)(2 * tp) * NU];
    float v1 = W[(size_t)(2 * tp + 1) * NU];
    uint32_t hi, lo;
    split_pair(v0, v1, hi, lo);
    g_WH[i] = hi;
    g_WL[i] = lo;
}

// ============================================================================
// K1: C[s][b] = X_s[b]^T @ [w2|w3]   M=128(d) N=128(u) K=1024(t)
// 8 warps (2M x 4N), warp tile 64x32, Kc=16 double-buffered cp.async.
// A: fp32 smem (stride 132), split at fragment load.
// B: pre-split packed fp16 words, direct LDS fragments (stride 136).
// ============================================================================
#define K1S 132
#define K1BS 136
__global__ void __launch_bounds__(256, 2) k1_xtw(const float* __restrict__ x1,
                                                 const float* __restrict__ x2) {
    __shared__ __align__(16) float sA[2][16][K1S];        // [t][d]
    __shared__ __align__(16) uint32_t sB[2][2][8][K1BS];  // [buf][hi/lo][t-pair][u]
    const int tid = threadIdx.x, wid = tid >> 5, lane = tid & 31;
    const int gid = lane >> 2, tig = lane & 3;
    const int dt = blockIdx.x, b = blockIdx.y, s = blockIdx.z;
    const float* __restrict__ X = s ? x2 : x1;
    const int d0 = dt * 128;
    const int wm = (wid >> 2) * 64, wn = (wid & 3) * 32;

    float acc[4][4][4];
#pragma unroll
    for (int i = 0; i < 4; i++)
#pragma unroll
        for (int j = 0; j < 4; j++)
#pragma unroll
            for (int q = 0; q < 4; q++) acc[i][j][q] = 0.f;

    const uint32_t aB = smem_u32(&sA[0][0][0]);
    const uint32_t bB = smem_u32(&sB[0][0][0][0]);
    const uint32_t aBuf = 16 * K1S * 4;
    const uint32_t bBuf = 2 * 8 * K1BS * 4;

    auto issue = [&](int ch, int bi) {
        const int k0 = ch * 16;
#pragma unroll
        for (int it = 0; it < 2; it++) {
            int ff = tid + it * 256;
            int r = ff >> 5, c = (ff & 31) * 4;
            cp16(aB + bi * aBuf + (uint32_t)(r * K1S + c) * 4,
                 X + ((size_t)b * NT + k0 + r) * ND + d0 + c);
        }
#pragma unroll
        for (int it = 0; it < 2; it++) {
            int ff = tid + it * 256;
            int sp = ff >> 8, r = (ff >> 5) & 7, c = (ff & 31) * 4;
            const uint32_t* src = (sp ? g_WL : g_WH) + (size_t)(ch * 8 + r) * 128 + c;
            cp16(bB + bi * bBuf + (uint32_t)((sp * 8 + r) * K1BS + c) * 4, src);
        }
        CP_COMMIT();
    };

    issue(0, 0);
    for (int ch = 0; ch < 64; ch++) {
        if (ch + 1 < 64) {
            issue(ch + 1, (ch + 1) & 1);
            CP_WAIT1();
        } else {
            CP_WAIT0();
        }
        __syncthreads();
        const int bi = ch & 1;
        const float(*A)[K1S] = sA[bi];
        uint32_t bh[4][2], bl[4][2];
#pragma unroll
        for (int ni = 0; ni < 4; ni++) {
            const int un = wn + ni * 8 + gid;
            bh[ni][0] = sB[bi][0][tig][un];
            bh[ni][1] = sB[bi][0][tig + 4][un];
            bl[ni][0] = sB[bi][1][tig][un];
            bl[ni][1] = sB[bi][1][tig + 4][un];
        }
#pragma unroll
        for (int mi = 0; mi < 4; mi++) {
            const int dm = wm + mi * 16 + gid;
            uint32_t ah[4], al[4];
            split_pair(A[2 * tig][dm], A[2 * tig + 1][dm], ah[0], al[0]);
            split_pair(A[2 * tig][dm + 8], A[2 * tig + 1][dm + 8], ah[1], al[1]);
            split_pair(A[2 * tig + 8][dm], A[2 * tig + 9][dm], ah[2], al[2]);
            split_pair(A[2 * tig + 8][dm + 8], A[2 * tig + 9][dm + 8], ah[3], al[3]);
#pragma unroll
            for (int ni = 0; ni < 4; ni++) {
                mma_f16(acc[mi][ni], ah, bh[ni]);
                mma_f16(acc[mi][ni], al, bh[ni]);
                mma_f16(acc[mi][ni], ah, bl[ni]);
            }
        }
        __syncthreads();
    }
    float* dst = g_C + (size_t)(s * NB + b) * ND * 128 + (size_t)d0 * 128;
#pragma unroll
    for (int mi = 0; mi < 4; mi++) {
        int r0 = wm + mi * 16 + gid, r1 = r0 + 8;
#pragma unroll
        for (int ni = 0; ni < 4; ni++) {
            int col = wn + ni * 8 + 2 * tig;
            *(float2*)(dst + (size_t)r0 * 128 + col) =
                make_float2(acc[mi][ni][0], acc[mi][ni][1]);
            *(float2*)(dst + (size_t)r1 * 128 + col) =
                make_float2(acc[mi][ni][2], acc[mi][ni][3]);
        }
    }
}

// ============================================================================
// K_prep: M[sb][d][u] = C[1-s][b][d][u] + C[s][b][d][64+u] + w1[d][u]
// -> packed f16x2 d-pair words g_MH/g_ML [sb][dp][u]
// ============================================================================
__global__ void __launch_bounds__(256) k_prep(const float* __restrict__ w1) {
    int i = blockIdx.x * 256 + threadIdx.x;  // 64*256*64 = 1,048,576
    int u = i & 63;
    int dp = (i >> 6) & 255;
    int sb = i >> 14;
    int s = sb >> 5, b = sb & 31;
    const float* C0 = g_C + ((size_t)((1 - s) * NB + b) * ND << 7);
    const float* C1 = g_C + ((size_t)sb * ND << 7);
    int d0 = 2 * dp, d1 = 2 * dp + 1;
    float m0 = C0[((size_t)d0 << 7) + u] + C1[((size_t)d0 << 7) + 64 + u] + w1[d0 * NU + u];
    float m1 = C0[((size_t)d1 << 7) + u] + C1[((size_t)d1 << 7) + 64 + u] + w1[d1 * NU + u];
    uint32_t hi, lo;
    split_pair(m0, m1, hi, lo);
    g_MH[i] = hi;
    g_ML[i] = lo;
}

// ============================================================================
// K2: e = 10*sum_u tanh(X@M)*we    M=256(t) N=64(u) K=512(d)
// grid 256 (single wave). 8 warps (4M x 2N), warp tile 64t x 32u, Kc=16.
// A: fp32 smem, split at fragment load. B: pre-split packed fp16 words.
// ============================================================================
#define K2AS 20
#define K2BS 72
__global__ void __launch_bounds__(256, 2) k2_he(const float* __restrict__ x1,
                                                const float* __restrict__ x2,
                                                const float* __restrict__ we) {
    __shared__ __align__(16) float sA[2][256][K2AS];      // [t][d]
    __shared__ __align__(16) uint32_t sB[2][2][8][K2BS];  // [buf][hi/lo][d-pair][u]
    __shared__ float wes[64];
    __shared__ float red[256][2];
    const int tid = threadIdx.x, wid = tid >> 5, lane = tid & 31;
    const int gid = lane >> 2, tig = lane & 3;
    const int tt = blockIdx.x, b = blockIdx.y, s = blockIdx.z;
    const float* __restrict__ X = s ? x2 : x1;
    const int t0 = tt * 256, sb = s * NB + b;
    const int wm = (wid >> 1) * 64, wn = (wid & 1) * 32;

    if (tid < 64) wes[tid] = we[tid];

    float acc[4][4][4];
#pragma unroll
    for (int i = 0; i < 4; i++)
#pragma unroll
        for (int j = 0; j < 4; j++)
#pragma unroll
            for (int q = 0; q < 4; q++) acc[i][j][q] = 0.f;

    const uint32_t aB = smem_u32(&sA[0][0][0]);
    const uint32_t bB = smem_u32(&sB[0][0][0][0]);
    const uint32_t aBuf = 256 * K2AS * 4;
    const uint32_t bBuf = 2 * 8 * K2BS * 4;
    const size_t mBase = (size_t)sb * 256 * 64;

    auto issue = [&](int ch, int bi) {
        const int k0 = ch * 16;
#pragma unroll
        for (int it = 0; it < 4; it++) {
            int ff = tid + it * 256;
            int r = ff >> 2, c = (ff & 3) * 4;
            cp16(aB + bi * aBuf + (uint32_t)(r * K2AS + c) * 4,
                 X + ((size_t)b * NT + t0 + r) * ND + k0 + c);
        }
        {
            int sp = tid >> 7, r = (tid >> 4) & 7, c = (tid & 15) * 4;
            const uint32_t* src = (sp ? g_ML : g_MH) + mBase + (size_t)(ch * 8 + r) * 64 + c;
            cp16(bB + bi * bBuf + (uint32_t)((sp * 8 + r) * K2BS + c) * 4, src);
        }
        CP_COMMIT();
    };

    issue(0, 0);
    for (int ch = 0; ch < 32; ch++) {
        if (ch + 1 < 32) {
            issue(ch + 1, (ch + 1) & 1);
            CP_WAIT1();
        } else {
            CP_WAIT0();
        }
        __syncthreads();
        const int bi = ch & 1;
        const float(*A)[K2AS] = sA[bi];
        uint32_t bh[4][2], bl[4][2];
#pragma unroll
        for (int ni = 0; ni < 4; ni++) {
            const int un = wn + ni * 8 + gid;
            bh[ni][0] = sB[bi][0][tig][un];
            bh[ni][1] = sB[bi][0][tig + 4][un];
            bl[ni][0] = sB[bi][1][tig][un];
            bl[ni][1] = sB[bi][1][tig + 4][un];
        }
#pragma unroll
        for (int mi = 0; mi < 4; mi++) {
            const int tr = wm + mi * 16 + gid;
            uint32_t ah[4], al[4];
            {
                float2 v = *(const float2*)&A[tr][2 * tig];
                split_pair(v.x, v.y, ah[0], al[0]);
            }
            {
                float2 v = *(const float2*)&A[tr + 8][2 * tig];
                split_pair(v.x, v.y, ah[1], al[1]);
            }
            {
                float2 v = *(const float2*)&A[tr][2 * tig + 8];
                split_pair(v.x, v.y, ah[2], al[2]);
            }
            {
                float2 v = *(const float2*)&A[tr + 8][2 * tig + 8];
                split_pair(v.x, v.y, ah[3], al[3]);
            }
#pragma unroll
            for (int ni = 0; ni < 4; ni++) {
                mma_f16(acc[mi][ni], ah, bh[ni]);
                mma_f16(acc[mi][ni], al, bh[ni]);
                mma_f16(acc[mi][ni], ah, bl[ni]);
            }
        }
        __syncthreads();
    }
    // epilogue: e(t) = 10 * sum_u tanh(h[t,u]) * we[u]
#pragma unroll
    for (int mi = 0; mi < 4; mi++) {
        int r0 = wm + mi * 16 + gid, r1 = r0 + 8;
        float p0 = 0.f, p1 = 0.f;
#pragma unroll
        for (int ni = 0; ni < 4; ni++) {
            int u = wn + ni * 8 + 2 * tig;
            p0 += tanhf(acc[mi][ni][0]) * wes[u] + tanhf(acc[mi][ni][1]) * wes[u + 1];
            p1 += tanhf(acc[mi][ni][2]) * wes[u] + tanhf(acc[mi][ni][3]) * wes[u + 1];
        }
        p0 += __shfl_xor_sync(0xffffffffu, p0, 1);
        p0 += __shfl_xor_sync(0xffffffffu, p0, 2);
        p1 += __shfl_xor_sync(0xffffffffu, p1, 1);
        p1 += __shfl_xor_sync(0xffffffffu, p1, 2);
        if (tig == 0) {
            red[r0][wid & 1] = p0;
            red[r1][wid & 1] = p1;
        }
    }
    __syncthreads();
    {
        g_E[sb * NT + t0 + tid] = 10.0f * (red[tid][0] + red[tid][1]);
    }
}

// ============================================================================
// K3: softmax over T per (s,b) (unstabilized, matches reference)
// ============================================================================
__global__ void __launch_bounds__(256) k3_softmax() {
    const int sb = blockIdx.x, tid = threadIdx.x;
    __shared__ float ssum[8];
    float a[4], lsum = 0.f;
#pragma unroll
    for (int i = 0; i < 4; i++) {
        a[i] = expf(g_E[sb * NT + tid + i * 256]);
        lsum += a[i];
    }
#pragma unroll
    for (int o = 16; o; o >>= 1) lsum += __shfl_xor_sync(0xffffffffu, lsum, o);
    if ((tid & 31) == 0) ssum[tid >> 5] = lsum;
    __syncthreads();
    if (tid == 0) {
        float sT = 0.f;
#pragma unroll
        for (int q = 0; q < 8; q++) sT += ssum[q];
        ssum[0] = 1.0f / (sT + 1e-7f);
    }
    __syncthreads();
    float inv = ssum[0];
#pragma unroll
    for (int i = 0; i < 4; i++) g_W[sb * NT + tid + i * 256] = a[i] * inv;
}

// ============================================================================
// K4: out = X * ww  (float4 streaming)
// ============================================================================
__global__ void __launch_bounds__(256) k4_scale(const float* __restrict__ x1,
                                                const float* __restrict__ x2,
                                                float* __restrict__ out) {
    size_t f = (size_t)blockIdx.x * 256 + threadIdx.x;
    int d4 = (int)(f & 127);
    int t = (int)((f >> 7) & 1023);
    int sb = (int)(f >> 17);
    const float* __restrict__ X = (sb >= NB) ? x2 : x1;
    int b = sb & 31;
    float w = g_W[sb * NT + t];
    float4 v = *(const float4*)(X + ((size_t)b * NT + t) * ND + (d4 << 2));
    v.x *= w; v.y *= w; v.z *= w; v.w *= w;
    ((float4*)out)[f] = v;
}

extern "C" void kernel_launch(void* const* d_in, const int* in_sizes, int n_in,
                              void* d_out, int out_size) {
    const float* x1 = (const float*)d_in[0];
    const float* x2 = (const float*)d_in[1];
    const float* w1 = (const float*)d_in[2];
    const float* w2 = (const float*)d_in[3];
    const float* w3 = (const float*)d_in[4];
    const float* we = (const float*)d_in[5];
    float* out = (float*)d_out;

    k0_wsplit<<<(512 * 128) / 256, 256>>>(w2, w3);

    dim3 g1(ND / 128, NB, 2);
    k1_xtw<<<g1, 256>>>(x1, x2);

    k_prep<<<(64 * 256 * 64) / 256, 256>>>(w1);

    dim3 g2(NT / 256, NB, 2);
    k2_he<<<g2, 256>>>(x1, x2, we);

    k3_softmax<<<2 * NB, 256>>>();

    k4_scale<<<(2u * NB * NT * (ND / 4)) / 256, 256>>>(x1, x2, out);
}

// round 13
// speedup vs baseline: 1.7538x; 1.0341x over previous
#include <cuda_runtime.h>
#include <cstdint>

#define NB 32
#define NT 1024
#define ND 512
#define NU 64

// -------- scratch (device globals) --------
__device__ float g_C[2ull * NB * ND * 128];   // X^T@[w2|w3] fp32  (16.8MB)
__device__ uint32_t g_WH[512 * 128];          // [t-pair][u] packed f16x2 hi of [w2|w3]
__device__ uint32_t g_WL[512 * 128];          //                  residual lo
__device__ uint32_t g_MH[64ull * 256 * 64];   // [sb][d-pair][u] packed f16x2 hi of M
__device__ uint32_t g_ML[64ull * 256 * 64];
__device__ float g_E[2 * NB * NT];
__device__ float g_W[2 * NB * NT];

// -------- helpers --------
__device__ __forceinline__ uint32_t smem_u32(const void* p) {
    uint32_t a;
    asm("{ .reg .u64 t; cvta.to.shared.u64 t, %1; cvt.u32.u64 %0, t; }" : "=r"(a) : "l"(p));
    return a;
}
// split (x0,x1) -> packed f16x2 hi (lo half = x0) + packed residual lo
__device__ __forceinline__ void split_pair(float x0, float x1, uint32_t& hi, uint32_t& lo) {
    asm("cvt.rn.f16x2.f32 %0, %1, %2;" : "=r"(hi) : "f"(x1), "f"(x0));
    float h0, h1;
    asm("{ .reg .b16 a, b; mov.b32 {a, b}, %2; cvt.f32.f16 %0, a; cvt.f32.f16 %1, b; }"
        : "=f"(h0), "=f"(h1) : "r"(hi));
    float l0 = x0 - h0, l1 = x1 - h1;
    asm("cvt.rn.f16x2.f32 %0, %1, %2;" : "=r"(lo) : "f"(l1), "f"(l0));
}
__device__ __forceinline__ void mma_f16(float* c, const uint32_t* a, const uint32_t* b) {
    asm volatile(
        "mma.sync.aligned.m16n8k16.row.col.f32.f16.f16.f32 "
        "{%0,%1,%2,%3}, {%4,%5,%6,%7}, {%8,%9}, {%0,%1,%2,%3};"
        : "+f"(c[0]), "+f"(c[1]), "+f"(c[2]), "+f"(c[3])
        : "r"(a[0]), "r"(a[1]), "r"(a[2]), "r"(a[3]), "r"(b[0]), "r"(b[1]));
}
__device__ __forceinline__ void cp16(uint32_t dst, const void* src) {
    asm volatile("cp.async.cg.shared.global [%0], [%1], 16;" :: "r"(dst), "l"(src));
}
#define CP_COMMIT() asm volatile("cp.async.commit_group;" ::: "memory")
#define CP_WAIT1() asm volatile("cp.async.wait_group 1;" ::: "memory")
#define CP_WAIT0() asm volatile("cp.async.wait_group 0;" ::: "memory")

// ============================================================================
// K0: pre-split [w2|w3] into packed f16x2 t-pair words.
// ============================================================================
__global__ void __launch_bounds__(256) k0_wsplit(const float* __restrict__ w2,
                                                 const float* __restrict__ w3) {
    int i = blockIdx.x * 256 + threadIdx.x;  // 512*128
    int u = i & 127, tp = i >> 7;
    const float* W = (u < 64) ? (w2 + u) : (w3 + (u - 64));
    float v0 = W[(size_t)(2 * tp) * NU];
    float v1 = W[(size_t)(2 * tp + 1) * NU];
    uint32_t hi, lo;
    split_pair(v0, v1, hi, lo);
    g_WH[i] = hi;
    g_WL[i] = lo;
}

// ============================================================================
// K1: C[s][b] = X_s[b]^T @ [w2|w3]   M=128(d) N=128(u) K=1024(t)
// 8 warps (2M x 4N), warp tile 64x32, Kc=16 double-buffered cp.async.
// A: fp32 smem (stride 132), split at fragment load.
// B: pre-split packed fp16 words, direct LDS fragments (stride 136).
// mma schedule: pass-major (hh x4ni, lh x4ni, hl x4ni) - 4-deep indep chains.
// ============================================================================
#define K1S 132
#define K1BS 136
__global__ void __launch_bounds__(256, 2) k1_xtw(const float* __restrict__ x1,
                                                 const float* __restrict__ x2) {
    __shared__ __align__(16) float sA[2][16][K1S];        // [t][d]
    __shared__ __align__(16) uint32_t sB[2][2][8][K1BS];  // [buf][hi/lo][t-pair][u]
    const int tid = threadIdx.x, wid = tid >> 5, lane = tid & 31;
    const int gid = lane >> 2, tig = lane & 3;
    const int dt = blockIdx.x, b = blockIdx.y, s = blockIdx.z;
    const float* __restrict__ X = s ? x2 : x1;
    const int d0 = dt * 128;
    const int wm = (wid >> 2) * 64, wn = (wid & 3) * 32;

    float acc[4][4][4];
#pragma unroll
    for (int i = 0; i < 4; i++)
#pragma unroll
        for (int j = 0; j < 4; j++)
#pragma unroll
            for (int q = 0; q < 4; q++) acc[i][j][q] = 0.f;

    const uint32_t aB = smem_u32(&sA[0][0][0]);
    const uint32_t bB = smem_u32(&sB[0][0][0][0]);
    const uint32_t aBuf = 16 * K1S * 4;
    const uint32_t bBuf = 2 * 8 * K1BS * 4;

    auto issue = [&](int ch, int bi) {
        const int k0 = ch * 16;
#pragma unroll
        for (int it = 0; it < 2; it++) {
            int ff = tid + it * 256;
            int r = ff >> 5, c = (ff & 31) * 4;
            cp16(aB + bi * aBuf + (uint32_t)(r * K1S + c) * 4,
                 X + ((size_t)b * NT + k0 + r) * ND + d0 + c);
        }
#pragma unroll
        for (int it = 0; it < 2; it++) {
            int ff = tid + it * 256;
            int sp = ff >> 8, r = (ff >> 5) & 7, c = (ff & 31) * 4;
            const uint32_t* src = (sp ? g_WL : g_WH) + (size_t)(ch * 8 + r) * 128 + c;
            cp16(bB + bi * bBuf + (uint32_t)((sp * 8 + r) * K1BS + c) * 4, src);
        }
        CP_COMMIT();
    };

    issue(0, 0);
    for (int ch = 0; ch < 64; ch++) {
        if (ch + 1 < 64) {
            issue(ch + 1, (ch + 1) & 1);
            CP_WAIT1();
        } else {
            CP_WAIT0();
        }
        __syncthreads();
        const int bi = ch & 1;
        const float(*A)[K1S] = sA[bi];
        uint32_t bh[4][2], bl[4][2];
#pragma unroll
        for (int ni = 0; ni < 4; ni++) {
            const int un = wn + ni * 8 + gid;
            bh[ni][0] = sB[bi][0][tig][un];
            bh[ni][1] = sB[bi][0][tig + 4][un];
            bl[ni][0] = sB[bi][1][tig][un];
            bl[ni][1] = sB[bi][1][tig + 4][un];
        }
#pragma unroll
        for (int mi = 0; mi < 4; mi++) {
            const int dm = wm + mi * 16 + gid;
            uint32_t ah[4], al[4];
            split_pair(A[2 * tig][dm], A[2 * tig + 1][dm], ah[0], al[0]);
            split_pair(A[2 * tig][dm + 8], A[2 * tig + 1][dm + 8], ah[1], al[1]);
            split_pair(A[2 * tig + 8][dm], A[2 * tig + 9][dm], ah[2], al[2]);
            split_pair(A[2 * tig + 8][dm + 8], A[2 * tig + 9][dm + 8], ah[3], al[3]);
            // pass-major: per-acc order stays hh -> lh -> hl (bit-identical),
            // but chains are 4 independent mmas apart.
#pragma unroll
            for (int ni = 0; ni < 4; ni++) mma_f16(acc[mi][ni], ah, bh[ni]);
#pragma unroll
            for (int ni = 0; ni < 4; ni++) mma_f16(acc[mi][ni], al, bh[ni]);
#pragma unroll
            for (int ni = 0; ni < 4; ni++) mma_f16(acc[mi][ni], ah, bl[ni]);
        }
        __syncthreads();
    }
    float* dst = g_C + (size_t)(s * NB + b) * ND * 128 + (size_t)d0 * 128;
#pragma unroll
    for (int mi = 0; mi < 4; mi++) {
        int r0 = wm + mi * 16 + gid, r1 = r0 + 8;
#pragma unroll
        for (int ni = 0; ni < 4; ni++) {
            int col = wn + ni * 8 + 2 * tig;
            *(float2*)(dst + (size_t)r0 * 128 + col) =
                make_float2(acc[mi][ni][0], acc[mi][ni][1]);
            *(float2*)(dst + (size_t)r1 * 128 + col) =
                make_float2(acc[mi][ni][2], acc[mi][ni][3]);
        }
    }
}

// ============================================================================
// K_prep: M[sb][d][u] = C[1-s][b][d][u] + C[s][b][d][64+u] + w1[d][u]
// -> packed f16x2 d-pair words g_MH/g_ML [sb][dp][u]
// ============================================================================
__global__ void __launch_bounds__(256) k_prep(const float* __restrict__ w1) {
    int i = blockIdx.x * 256 + threadIdx.x;  // 64*256*64 = 1,048,576
    int u = i & 63;
    int dp = (i >> 6) & 255;
    int sb = i >> 14;
    int s = sb >> 5, b = sb & 31;
    const float* C0 = g_C + ((size_t)((1 - s) * NB + b) * ND << 7);
    const float* C1 = g_C + ((size_t)sb * ND << 7);
    int d0 = 2 * dp, d1 = 2 * dp + 1;
    float m0 = C0[((size_t)d0 << 7) + u] + C1[((size_t)d0 << 7) + 64 + u] + w1[d0 * NU + u];
    float m1 = C0[((size_t)d1 << 7) + u] + C1[((size_t)d1 << 7) + 64 + u] + w1[d1 * NU + u];
    uint32_t hi, lo;
    split_pair(m0, m1, hi, lo);
    g_MH[i] = hi;
    g_ML[i] = lo;
}

// ============================================================================
// K2: e = 10*sum_u tanh(X@M)*we    M=256(t) N=64(u) K=512(d)
// grid 256 (single wave). 8 warps (4M x 2N), warp tile 64t x 32u, Kc=16.
// A: fp32 smem, split at fragment load. B: pre-split packed fp16 words.
// mma schedule: pass-major per mi (4-deep independent chains).
// ============================================================================
#define K2AS 20
#define K2BS 72
__global__ void __launch_bounds__(256, 2) k2_he(const float* __restrict__ x1,
                                                const float* __restrict__ x2,
                                                const float* __restrict__ we) {
    __shared__ __align__(16) float sA[2][256][K2AS];      // [t][d]
    __shared__ __align__(16) uint32_t sB[2][2][8][K2BS];  // [buf][hi/lo][d-pair][u]
    __shared__ float wes[64];
    __shared__ float red[256][2];
    const int tid = threadIdx.x, wid = tid >> 5, lane = tid & 31;
    const int gid = lane >> 2, tig = lane & 3;
    const int tt = blockIdx.x, b = blockIdx.y, s = blockIdx.z;
    const float* __restrict__ X = s ? x2 : x1;
    const int t0 = tt * 256, sb = s * NB + b;
    const int wm = (wid >> 1) * 64, wn = (wid & 1) * 32;

    if (tid < 64) wes[tid] = we[tid];

    float acc[4][4][4];
#pragma unroll
    for (int i = 0; i < 4; i++)
#pragma unroll
        for (int j = 0; j < 4; j++)
#pragma unroll
            for (int q = 0; q < 4; q++) acc[i][j][q] = 0.f;

    const uint32_t aB = smem_u32(&sA[0][0][0]);
    const uint32_t bB = smem_u32(&sB[0][0][0][0]);
    const uint32_t aBuf = 256 * K2AS * 4;
    const uint32_t bBuf = 2 * 8 * K2BS * 4;
    const size_t mBase = (size_t)sb * 256 * 64;

    auto issue = [&](int ch, int bi) {
        const int k0 = ch * 16;
#pragma unroll
        for (int it = 0; it < 4; it++) {
            int ff = tid + it * 256;
            int r = ff >> 2, c = (ff & 3) * 4;
            cp16(aB + bi * aBuf + (uint32_t)(r * K2AS + c) * 4,
                 X + ((size_t)b * NT + t0 + r) * ND + k0 + c);
        }
        {
            int sp = tid >> 7, r = (tid >> 4) & 7, c = (tid & 15) * 4;
            const uint32_t* src = (sp ? g_ML : g_MH) + mBase + (size_t)(ch * 8 + r) * 64 + c;
            cp16(bB + bi * bBuf + (uint32_t)((sp * 8 + r) * K2BS + c) * 4, src);
        }
        CP_COMMIT();
    };

    issue(0, 0);
    for (int ch = 0; ch < 32; ch++) {
        if (ch + 1 < 32) {
            issue(ch + 1, (ch + 1) & 1);
            CP_WAIT1();
        } else {
            CP_WAIT0();
        }
        __syncthreads();
        const int bi = ch & 1;
        const float(*A)[K2AS] = sA[bi];
        uint32_t bh[4][2], bl[4][2];
#pragma unroll
        for (int ni = 0; ni < 4; ni++) {
            const int un = wn + ni * 8 + gid;
            bh[ni][0] = sB[bi][0][tig][un];
            bh[ni][1] = sB[bi][0][tig + 4][un];
            bl[ni][0] = sB[bi][1][tig][un];
            bl[ni][1] = sB[bi][1][tig + 4][un];
        }
#pragma unroll
        for (int mi = 0; mi < 4; mi++) {
            const int tr = wm + mi * 16 + gid;
            uint32_t ah[4], al[4];
            {
                float2 v = *(const float2*)&A[tr][2 * tig];
                split_pair(v.x, v.y, ah[0], al[0]);
            }
            {
                float2 v = *(const float2*)&A[tr + 8][2 * tig];
                split_pair(v.x, v.y, ah[1], al[1]);
            }
            {
                float2 v = *(const float2*)&A[tr][2 * tig + 8];
                split_pair(v.x, v.y, ah[2], al[2]);
            }
            {
                float2 v = *(const float2*)&A[tr + 8][2 * tig + 8];
                split_pair(v.x, v.y, ah[3], al[3]);
            }
#pragma unroll
            for (int ni = 0; ni < 4; ni++) mma_f16(acc[mi][ni], ah, bh[ni]);
#pragma unroll
            for (int ni = 0; ni < 4; ni++) mma_f16(acc[mi][ni], al, bh[ni]);
#pragma unroll
            for (int ni = 0; ni < 4; ni++) mma_f16(acc[mi][ni], ah, bl[ni]);
        }
        __syncthreads();
    }
    // epilogue: e(t) = 10 * sum_u tanh(h[t,u]) * we[u]
#pragma unroll
    for (int mi = 0; mi < 4; mi++) {
        int r0 = wm + mi * 16 + gid, r1 = r0 + 8;
        float p0 = 0.f, p1 = 0.f;
#pragma unroll
        for (int ni = 0; ni < 4; ni++) {
            int u = wn + ni * 8 + 2 * tig;
            p0 += tanhf(acc[mi][ni][0]) * wes[u] + tanhf(acc[mi][ni][1]) * wes[u + 1];
            p1 += tanhf(acc[mi][ni][2]) * wes[u] + tanhf(acc[mi][ni][3]) * wes[u + 1];
        }
        p0 += __shfl_xor_sync(0xffffffffu, p0, 1);
        p0 += __shfl_xor_sync(0xffffffffu, p0, 2);
        p1 += __shfl_xor_sync(0xffffffffu, p1, 1);
        p1 += __shfl_xor_sync(0xffffffffu, p1, 2);
        if (tig == 0) {
            red[r0][wid & 1] = p0;
            red[r1][wid & 1] = p1;
        }
    }
    __syncthreads();
    {
        g_E[sb * NT + t0 + tid] = 10.0f * (red[tid][0] + red[tid][1]);
    }
}

// ============================================================================
// K3: softmax over T per (s,b) (unstabilized, matches reference)
// ============================================================================
__global__ void __launch_bounds__(256) k3_softmax() {
    const int sb = blockIdx.x, tid = threadIdx.x;
    __shared__ float ssum[8];
    float a[4], lsum = 0.f;
#pragma unroll
    for (int i = 0; i < 4; i++) {
        a[i] = expf(g_E[sb * NT + tid + i * 256]);
        lsum += a[i];
    }
#pragma unroll
    for (int o = 16; o; o >>= 1) lsum += __shfl_xor_sync(0xffffffffu, lsum, o);
    if ((tid & 31) == 0) ssum[tid >> 5] = lsum;
    __syncthreads();
    if (tid == 0) {
        float sT = 0.f;
#pragma unroll
        for (int q = 0; q < 8; q++) sT += ssum[q];
        ssum[0] = 1.0f / (sT + 1e-7f);
    }
    __syncthreads();
    float inv = ssum[0];
#pragma unroll
    for (int i = 0; i < 4; i++) g_W[sb * NT + tid + i * 256] = a[i] * inv;
}

// ============================================================================
// K4: out = X * ww  (float4 streaming)
// ============================================================================
__global__ void __launch_bounds__(256) k4_scale(const float* __restrict__ x1,
                                                const float* __restrict__ x2,
                                                float* __restrict__ out) {
    size_t f = (size_t)blockIdx.x * 256 + threadIdx.x;
    int d4 = (int)(f & 127);
    int t = (int)((f >> 7) & 1023);
    int sb = (int)(f >> 17);
    const float* __restrict__ X = (sb >= NB) ? x2 : x1;
    int b = sb & 31;
    float w = g_W[sb * NT + t];
    float4 v = *(const float4*)(X + ((size_t)b * NT + t) * ND + (d4 << 2));
    v.x *= w; v.y *= w; v.z *= w; v.w *= w;
    ((float4*)out)[f] = v;
}

extern "C" void kernel_launch(void* const* d_in, const int* in_sizes, int n_in,
                              void* d_out, int out_size) {
    const float* x1 = (const float*)d_in[0];
    const float* x2 = (const float*)d_in[1];
    const float* w1 = (const float*)d_in[2];
    const float* w2 = (const float*)d_in[3];
    const float* w3 = (const float*)d_in[4];
    const float* we = (const float*)d_in[5];
    float* out = (float*)d_out;

    k0_wsplit<<<(512 * 128) / 256, 256>>>(w2, w3);

    dim3 g1(ND / 128, NB, 2);
    k1_xtw<<<g1, 256>>>(x1, x2);

    k_prep<<<(64 * 256 * 64) / 256, 256>>>(w1);

    dim3 g2(NT / 256, NB, 2);
    k2_he<<<g2, 256>>>(x1, x2, we);

    k3_softmax<<<2 * NB, 256>>>();

    k4_scale<<<(2u * NB * NT * (ND / 4)) / 256, 256>>>(x1, x2, out);
}